// round 1
// baseline (speedup 1.0000x reference)
#include <cuda_runtime.h>
#include <cuda_bf16.h>
#include <math.h>

// ---------------- problem constants ----------------
#define T_    2048
#define HID_  2048
#define H_    16
#define DN_   128
#define DR_   64
#define DQK_  192
#define DV_   128
#define QLR_  1536
#define KVLR_ 512
#define INTER_ 10944
#define EPS_  1e-6f

// ---------------- scratch (static device globals; no allocation) -------------
__device__ float g_h[(size_t)T_ * HID_];          // normed hidden, later reused for o-proj out & down out
__device__ float g_qa[(size_t)T_ * QLR_];
__device__ float g_q[(size_t)T_ * H_ * DQK_];
__device__ float g_ckv[(size_t)T_ * (KVLR_ + DR_)];
__device__ float g_ckvn[(size_t)T_ * KVLR_];
__device__ float g_kv[(size_t)T_ * H_ * (DN_ + DV_)];
__device__ float g_qfull[(size_t)H_ * T_ * DQK_];
__device__ float g_kfull[(size_t)H_ * T_ * DQK_];
__device__ float g_scores[(size_t)H_ * T_ * T_];  // 256 MB, reused as probs
__device__ float g_vt[(size_t)H_ * DV_ * T_];
__device__ float g_attn[(size_t)T_ * H_ * DV_];
__device__ float g_res2[(size_t)T_ * HID_];
__device__ float g_h2[(size_t)T_ * HID_];
__device__ float g_gate[(size_t)T_ * INTER_];
__device__ float g_up[(size_t)T_ * INTER_];

// ---------------- generic batched SGEMM: C = A * B^T ----------------
// A: [M,K] row-major (lda), B: [N,K] row-major (ldb), C: [M,N] (ldc)
// mode 0: dense; mode 1: causal-scores (skip tiles fully above diagonal, M/N both seq);
// mode 2: causal-PV (K dim is key index; truncate K loop to this row-block's max key).
#define BM 128
#define BN 128
#define BK 8
#define TM 8
#define TN 8

__global__ __launch_bounds__(256) void gemm_tn(
    const float* __restrict__ A, int lda, size_t sA,
    const float* __restrict__ B, int ldb, size_t sB,
    float* __restrict__ C, int ldc, size_t sC,
    int M, int N, int K, int mode)
{
    const int bm = blockIdx.y, bn = blockIdx.x, bz = blockIdx.z;
    if (mode == 1 && bn * BN > bm * BM + (BM - 1)) return;  // fully masked tile
    int kEnd = K;
    if (mode == 2) { int ke = (bm + 1) * BM; kEnd = ke < K ? ke : K; }

    A += (size_t)bz * sA;
    B += (size_t)bz * sB;
    C += (size_t)bz * sC;

    __shared__ float As[BK][BM];
    __shared__ float Bs[BK][BN];

    const int tid = threadIdx.x;
    const int ar = tid >> 1;           // 0..127
    const int ac = (tid & 1) * 4;      // 0 or 4
    const int tx = tid & 15;
    const int ty = tid >> 4;

    const bool fullN = (bn * BN + BN) <= N;
    const int brow = bn * BN + ar;

    float acc[TM][TN];
#pragma unroll
    for (int i = 0; i < TM; i++)
#pragma unroll
        for (int j = 0; j < TN; j++) acc[i][j] = 0.f;

    for (int k0 = 0; k0 < kEnd; k0 += BK) {
        // load A tile (M always multiple of 128 in this problem)
        float4 av = *(const float4*)(A + (size_t)(bm * BM + ar) * lda + k0 + ac);
        As[ac + 0][ar] = av.x; As[ac + 1][ar] = av.y;
        As[ac + 2][ar] = av.z; As[ac + 3][ar] = av.w;
        // load B tile with N guard
        float4 bv = make_float4(0.f, 0.f, 0.f, 0.f);
        if (fullN || brow < N)
            bv = *(const float4*)(B + (size_t)brow * ldb + k0 + ac);
        Bs[ac + 0][ar] = bv.x; Bs[ac + 1][ar] = bv.y;
        Bs[ac + 2][ar] = bv.z; Bs[ac + 3][ar] = bv.w;
        __syncthreads();

#pragma unroll
        for (int kk = 0; kk < BK; kk++) {
            float ra[TM], rb[TN];
#pragma unroll
            for (int i = 0; i < TM; i++) ra[i] = As[kk][ty * TM + i];
#pragma unroll
            for (int j = 0; j < TN; j++) rb[j] = Bs[kk][tx * TN + j];
#pragma unroll
            for (int i = 0; i < TM; i++)
#pragma unroll
                for (int j = 0; j < TN; j++)
                    acc[i][j] = fmaf(ra[i], rb[j], acc[i][j]);
        }
        __syncthreads();
    }

    const int row0 = bm * BM + ty * TM;
    const int col0 = bn * BN + tx * TN;
#pragma unroll
    for (int i = 0; i < TM; i++) {
        float* crow = C + (size_t)(row0 + i) * ldc;
#pragma unroll
        for (int j = 0; j < TN; j++) {
            int c = col0 + j;
            if (c < N) crow[c] = acc[i][j];
        }
    }
}

// ---------------- rmsnorm ----------------
__global__ void rmsnorm_kernel(const float* __restrict__ x, int ldx,
                               const float* __restrict__ w,
                               float* __restrict__ out, int ldo, int dim)
{
    const int row = blockIdx.x;
    const float* xr = x + (size_t)row * ldx;
    float ss = 0.f;
    for (int i = threadIdx.x; i < dim; i += blockDim.x) { float v = xr[i]; ss += v * v; }
    __shared__ float red[256];
    red[threadIdx.x] = ss;
    __syncthreads();
    for (int s = 128; s > 0; s >>= 1) {
        if (threadIdx.x < s) red[threadIdx.x] += red[threadIdx.x + s];
        __syncthreads();
    }
    const float inv = rsqrtf(red[0] / (float)dim + EPS_);
    float* o = out + (size_t)row * ldo;
    for (int i = threadIdx.x; i < dim; i += blockDim.x) o[i] = xr[i] * inv * w[i];
}

// ---------------- RoPE + pack q_full / k_full as [H][T][DQK] ----------------
__global__ void rope_pack_kernel(const float* __restrict__ q,
                                 const float* __restrict__ kv,
                                 const float* __restrict__ ckv,
                                 const float* __restrict__ cosb,
                                 const float* __restrict__ sinb,
                                 float* __restrict__ qfull,
                                 float* __restrict__ kfull)
{
    const int t = blockIdx.x, h = blockIdx.y, j = threadIdx.x;  // j in [0,192)
    const size_t o = ((size_t)h * T_ + t) * DQK_ + j;
    float qv, kvv;
    if (j < DN_) {
        qv  = q[(size_t)t * (H_ * DQK_) + h * DQK_ + j];
        kvv = kv[(size_t)t * (H_ * (DN_ + DV_)) + h * (DN_ + DV_) + j];
    } else {
        const int jj = j - DN_;                 // 0..63
        const int p  = (jj < DR_ / 2) ? jj : jj - DR_ / 2;
        const float c = cosb[(size_t)t * DR_ + jj];
        const float s = sinb[(size_t)t * DR_ + jj];
        const size_t qb = (size_t)t * (H_ * DQK_) + h * DQK_ + DN_;
        const size_t kb = (size_t)t * (KVLR_ + DR_) + KVLR_;
        const float qe = q[qb + 2 * p], qo = q[qb + 2 * p + 1];
        const float ke = ckv[kb + 2 * p], ko = ckv[kb + 2 * p + 1];
        if (jj < DR_ / 2) { qv = qe * c - qo * s;  kvv = ke * c - ko * s; }
        else              { qv = qo * c + qe * s;  kvv = ko * c + ke * s; }
    }
    qfull[o] = qv;
    kfull[o] = kvv;
}

// ---------------- causal softmax in place (scores -> probs) ----------------
__global__ void softmax_causal_kernel(float* __restrict__ scores)
{
    const int q = blockIdx.x, h = blockIdx.y;
    float* row = scores + ((size_t)h * T_ + q) * T_;
    const int len = q + 1;
    const float scale = 0.07216878364870323f;  // 192^-0.5
    const int tid = threadIdx.x;
    __shared__ float red[256];

    float m = -INFINITY;
    for (int i = tid; i < len; i += 256) m = fmaxf(m, row[i] * scale);
    red[tid] = m; __syncthreads();
    for (int s = 128; s > 0; s >>= 1) {
        if (tid < s) red[tid] = fmaxf(red[tid], red[tid + s]);
        __syncthreads();
    }
    m = red[0]; __syncthreads();

    float sum = 0.f;
    for (int i = tid; i < len; i += 256) {
        float e = expf(row[i] * scale - m);
        row[i] = e;
        sum += e;
    }
    red[tid] = sum; __syncthreads();
    for (int s = 128; s > 0; s >>= 1) {
        if (tid < s) red[tid] += red[tid + s];
        __syncthreads();
    }
    const float rinv = 1.f / red[0];
    for (int i = tid; i < len; i += 256) row[i] *= rinv;
    // zero the tail up to the 128-aligned boundary the PV GEMM will read
    const int bound = ((q / BM) + 1) * BM;
    for (int i = len + tid; i < bound; i += 256) row[i] = 0.f;
}

// ---------------- pack V^T as [H][DV][T] ----------------
__global__ void pack_vt_kernel(const float* __restrict__ kv, float* __restrict__ vt)
{
    size_t i = (size_t)blockIdx.x * blockDim.x + threadIdx.x;
    const size_t n = (size_t)H_ * DV_ * T_;
    if (i >= n) return;
    const int t = (int)(i % T_);
    const size_t r = i / T_;
    const int d = (int)(r % DV_);
    const int h = (int)(r / DV_);
    vt[i] = kv[(size_t)t * (H_ * (DN_ + DV_)) + h * (DN_ + DV_) + DN_ + d];
}

// ---------------- elementwise ----------------
__global__ void add_kernel(const float* __restrict__ a, const float* __restrict__ b,
                           float* __restrict__ o, size_t n)
{
    size_t i = (size_t)blockIdx.x * blockDim.x + threadIdx.x;
    if (i < n) o[i] = a[i] + b[i];
}

__global__ void silu_mul_kernel(float* __restrict__ gate, const float* __restrict__ up, size_t n)
{
    size_t i = (size_t)blockIdx.x * blockDim.x + threadIdx.x;
    if (i < n) {
        float g = gate[i];
        gate[i] = (g / (1.f + expf(-g))) * up[i];
    }
}

// ---------------- host driver ----------------
static inline void* sym(const void* s)
{
    void* p = nullptr;
    cudaGetSymbolAddress(&p, s);
    return p;
}

extern "C" void kernel_launch(void* const* d_in, const int* in_sizes, int n_in,
                              void* d_out, int out_size)
{
    const float* hidden  = (const float*)d_in[0];
    const float* cosb    = (const float*)d_in[1];
    const float* sinb    = (const float*)d_in[2];
    const float* ln_in   = (const float*)d_in[3];
    const float* w_q_a   = (const float*)d_in[4];
    const float* ln_q_a  = (const float*)d_in[5];
    const float* w_q_b   = (const float*)d_in[6];
    const float* w_kv_a  = (const float*)d_in[7];
    const float* ln_kv_a = (const float*)d_in[8];
    const float* w_kv_b  = (const float*)d_in[9];
    const float* w_o     = (const float*)d_in[10];
    const float* ln_post = (const float*)d_in[11];
    const float* w_gate  = (const float*)d_in[12];
    const float* w_up    = (const float*)d_in[13];
    const float* w_down  = (const float*)d_in[14];
    float* out = (float*)d_out;

    float* h     = (float*)sym(g_h);
    float* qa    = (float*)sym(g_qa);
    float* q     = (float*)sym(g_q);
    float* ckv   = (float*)sym(g_ckv);
    float* ckvn  = (float*)sym(g_ckvn);
    float* kv    = (float*)sym(g_kv);
    float* qfull = (float*)sym(g_qfull);
    float* kfull = (float*)sym(g_kfull);
    float* sc    = (float*)sym(g_scores);
    float* vt    = (float*)sym(g_vt);
    float* attn  = (float*)sym(g_attn);
    float* res2  = (float*)sym(g_res2);
    float* h2    = (float*)sym(g_h2);
    float* gate  = (float*)sym(g_gate);
    float* up    = (float*)sym(g_up);

    const int NB = 256;
    auto grid2 = [](int M, int N) { return dim3((N + BN - 1) / BN, M / BM, 1); };

    // 1. input rmsnorm
    rmsnorm_kernel<<<T_, NB>>>(hidden, HID_, ln_in, h, HID_, HID_);
    // 2. q_a = h @ w_q_a^T
    gemm_tn<<<grid2(T_, QLR_), NB>>>(h, HID_, 0, w_q_a, HID_, 0, qa, QLR_, 0, T_, QLR_, HID_, 0);
    // 3. rmsnorm q_a (in place)
    rmsnorm_kernel<<<T_, NB>>>(qa, QLR_, ln_q_a, qa, QLR_, QLR_);
    // 4. q = qa @ w_q_b^T
    gemm_tn<<<grid2(T_, H_ * DQK_), NB>>>(qa, QLR_, 0, w_q_b, QLR_, 0, q, H_ * DQK_, 0, T_, H_ * DQK_, QLR_, 0);
    // 5. ckv = h @ w_kv_a^T
    gemm_tn<<<grid2(T_, KVLR_ + DR_), NB>>>(h, HID_, 0, w_kv_a, HID_, 0, ckv, KVLR_ + DR_, 0, T_, KVLR_ + DR_, HID_, 0);
    // 6. rmsnorm c_kv slice
    rmsnorm_kernel<<<T_, NB>>>(ckv, KVLR_ + DR_, ln_kv_a, ckvn, KVLR_, KVLR_);
    // 7. kv = ckvn @ w_kv_b^T
    gemm_tn<<<grid2(T_, H_ * (DN_ + DV_)), NB>>>(ckvn, KVLR_, 0, w_kv_b, KVLR_, 0, kv, H_ * (DN_ + DV_), 0,
                                                 T_, H_ * (DN_ + DV_), KVLR_, 0);
    // 8. RoPE + pack
    rope_pack_kernel<<<dim3(T_, H_), DQK_>>>(q, kv, ckv, cosb, sinb, qfull, kfull);
    // 9. scores = q_full @ k_full^T (per head, causal tile skip)
    gemm_tn<<<dim3(T_ / BN, T_ / BM, H_), NB>>>(qfull, DQK_, (size_t)T_ * DQK_,
                                                kfull, DQK_, (size_t)T_ * DQK_,
                                                sc, T_, (size_t)T_ * T_,
                                                T_, T_, DQK_, 1);
    // 10. causal softmax
    softmax_causal_kernel<<<dim3(T_, H_), NB>>>(sc);
    // 11. pack V^T
    {
        size_t n = (size_t)H_ * DV_ * T_;
        pack_vt_kernel<<<(unsigned)((n + NB - 1) / NB), NB>>>(kv, vt);
    }
    // 12. attn = probs @ V  (write directly into [T, H*DV] layout)
    gemm_tn<<<dim3(1, T_ / BM, H_), NB>>>(sc, T_, (size_t)T_ * T_,
                                          vt, T_, (size_t)DV_ * T_,
                                          attn, H_ * DV_, (size_t)DV_,
                                          T_, DV_, T_, 2);
    // 13. o = attn @ w_o^T   (reuse h as o-buffer)
    gemm_tn<<<grid2(T_, HID_), NB>>>(attn, H_ * DV_, 0, w_o, H_ * DV_, 0, h, HID_, 0, T_, HID_, H_ * DV_, 0);
    // 14. res2 = hidden + o
    {
        size_t n = (size_t)T_ * HID_;
        add_kernel<<<(unsigned)((n + NB - 1) / NB), NB>>>(hidden, h, res2, n);
    }
    // 15. h2 = rmsnorm(res2, ln_post)
    rmsnorm_kernel<<<T_, NB>>>(res2, HID_, ln_post, h2, HID_, HID_);
    // 16/17. gate, up
    gemm_tn<<<grid2(T_, INTER_), NB>>>(h2, HID_, 0, w_gate, HID_, 0, gate, INTER_, 0, T_, INTER_, HID_, 0);
    gemm_tn<<<grid2(T_, INTER_), NB>>>(h2, HID_, 0, w_up, HID_, 0, up, INTER_, 0, T_, INTER_, HID_, 0);
    // 18. act = silu(gate) * up (in place in gate)
    {
        size_t n = (size_t)T_ * INTER_;
        silu_mul_kernel<<<(unsigned)((n + NB - 1) / NB), NB>>>(gate, up, n);
    }
    // 19. down = act @ w_down^T (reuse h)
    gemm_tn<<<grid2(T_, HID_), NB>>>(gate, INTER_, 0, w_down, INTER_, 0, h, HID_, 0, T_, HID_, INTER_, 0);
    // 20. out = res2 + down
    {
        size_t n = (size_t)T_ * HID_;
        add_kernel<<<(unsigned)((n + NB - 1) / NB), NB>>>(res2, h, out, n);
    }
}

// round 2
// speedup vs baseline: 2.8733x; 2.8733x over previous
#include <cuda_runtime.h>
#include <cuda_bf16.h>
#include <math.h>
#include <stdint.h>

// ---------------- problem constants ----------------
#define T_    2048
#define HID_  2048
#define H_    16
#define DN_   128
#define DR_   64
#define DQK_  192
#define DV_   128
#define QLR_  1536
#define KVLR_ 512
#define INTER_ 10944
#define EPS_  1e-6f

// ---------------- scratch (static device globals; no allocation) -------------
__device__ float g_h[(size_t)T_ * HID_];
__device__ float g_qa[(size_t)T_ * QLR_];
__device__ float g_q[(size_t)T_ * H_ * DQK_];
__device__ float g_ckv[(size_t)T_ * (KVLR_ + DR_)];
__device__ float g_ckvn[(size_t)T_ * KVLR_];
__device__ float g_kv[(size_t)T_ * H_ * (DN_ + DV_)];
__device__ float g_qfull[(size_t)H_ * T_ * DQK_];
__device__ float g_kfull[(size_t)H_ * T_ * DQK_];
__device__ float g_scores[(size_t)H_ * T_ * T_];  // reused as probs
__device__ float g_vt[(size_t)H_ * DV_ * T_];
__device__ float g_attn[(size_t)T_ * H_ * DV_];
__device__ float g_res2[(size_t)T_ * HID_];
__device__ float g_h2[(size_t)T_ * HID_];
__device__ float g_gate[(size_t)T_ * INTER_];
__device__ float g_up[(size_t)T_ * INTER_];

// =====================================================================
// TF32 tensor-core GEMM:  C = A * B^T
// A: [M,K] row-major (lda), B: [N,K] row-major (ldb), C: [M,N] (ldc)
// Block tile 128x128, BK=16, 8 warps (2x4), warp tile 64x32 via m16n8k8.
// mode 0: dense; mode 1: causal (skip fully-masked tiles);
// mode 2: causal-PV (truncate K loop to (bm+1)*128).
// Requirements (all satisfied by this problem): M%128==0, K%16==0,
// K-pointers 16B aligned, N even.
// =====================================================================

__device__ __forceinline__ uint32_t f2tf32(float f) {
    uint32_t u;
    asm("cvt.rna.tf32.f32 %0, %1;" : "=r"(u) : "f"(f));
    return u;
}

__device__ __forceinline__ uint4 ld_cvt(const float* p) {
    float4 v = *(const float4*)p;
    uint4 u;
    u.x = f2tf32(v.x); u.y = f2tf32(v.y);
    u.z = f2tf32(v.z); u.w = f2tf32(v.w);
    return u;
}

__device__ __forceinline__ void ldsm4(uint32_t addr, uint32_t& r0, uint32_t& r1,
                                      uint32_t& r2, uint32_t& r3) {
    asm volatile("ldmatrix.sync.aligned.m8n8.x4.shared.b16 {%0,%1,%2,%3}, [%4];"
                 : "=r"(r0), "=r"(r1), "=r"(r2), "=r"(r3) : "r"(addr));
}

__device__ __forceinline__ void mma_tf32(float* c, const uint32_t* a, const uint32_t* b) {
    asm volatile(
        "mma.sync.aligned.m16n8k8.row.col.f32.tf32.tf32.f32 "
        "{%0,%1,%2,%3}, {%4,%5,%6,%7}, {%8,%9}, {%0,%1,%2,%3};"
        : "+f"(c[0]), "+f"(c[1]), "+f"(c[2]), "+f"(c[3])
        : "r"(a[0]), "r"(a[1]), "r"(a[2]), "r"(a[3]), "r"(b[0]), "r"(b[1]));
}

// swizzled uint4 index inside a 128-row x 4-chunk tile
__device__ __forceinline__ int swz(int row, int chunk) {
    return row * 4 + (chunk ^ ((row >> 1) & 3));
}

__global__ __launch_bounds__(256) void gemm_tf32(
    const float* __restrict__ A, int lda, size_t sA,
    const float* __restrict__ B, int ldb, size_t sB,
    float* __restrict__ C, int ldc, size_t sC,
    int M, int N, int K, int mode)
{
    const int bm = blockIdx.y, bn = blockIdx.x, bz = blockIdx.z;
    if (mode == 1 && bn > bm) return;
    int kEnd = K;
    if (mode == 2) { int ke = (bm + 1) * 128; kEnd = ke < K ? ke : K; }

    A += (size_t)bz * sA;
    B += (size_t)bz * sB;
    C += (size_t)bz * sC;

    __shared__ uint4 smA[2][512];   // [buf][128 rows * 4 chunks] (8KB each)
    __shared__ uint4 smB[2][512];

    const int tid = threadIdx.x;
    const int wid = tid >> 5, lane = tid & 31;
    const int wm = wid & 1, wn = wid >> 1;

    // ---- loader mapping: thread -> (row = tid/4 [+64], chunk = tid%4) ----
    const int lr = tid >> 2;
    const int lc = tid & 3;
    const float* gA0 = A + (size_t)((size_t)bm * 128 + lr) * lda + lc * 4;
    const float* gA1 = gA0 + (size_t)64 * lda;
    const int nrow0 = bn * 128 + lr, nrow1 = nrow0 + 64;
    const float* gB0 = B + (size_t)nrow0 * ldb + lc * 4;
    const float* gB1 = B + (size_t)nrow1 * ldb + lc * 4;
    const bool vB0 = nrow0 < N, vB1 = nrow1 < N;

    const int dA0 = swz(lr, lc), dA1 = swz(lr + 64, lc);

    float acc[4][4][4];
#pragma unroll
    for (int i = 0; i < 4; i++)
#pragma unroll
        for (int j = 0; j < 4; j++)
#pragma unroll
            for (int l = 0; l < 4; l++) acc[i][j][l] = 0.f;

    const uint4 z4 = make_uint4(0u, 0u, 0u, 0u);

    // prologue: tile 0
    {
        uint4 ra0 = ld_cvt(gA0), ra1 = ld_cvt(gA1);
        uint4 rb0 = vB0 ? ld_cvt(gB0) : z4;
        uint4 rb1 = vB1 ? ld_cvt(gB1) : z4;
        smA[0][dA0] = ra0; smA[0][dA1] = ra1;
        smB[0][dA0] = rb0; smB[0][dA1] = rb1;
    }
    __syncthreads();

    uint32_t baseA = (uint32_t)__cvta_generic_to_shared(&smA[0][0]);
    uint32_t baseB = (uint32_t)__cvta_generic_to_shared(&smB[0][0]);

    const int nIter = kEnd >> 4;
    uint4 ra0, ra1, rb0, rb1;

    for (int it = 0; it < nIter; ++it) {
        const int buf = it & 1;
        const bool more = (it + 1) < nIter;
        if (more) {
            const int ko = (it + 1) * 16;
            ra0 = ld_cvt(gA0 + ko);
            ra1 = ld_cvt(gA1 + ko);
            rb0 = vB0 ? ld_cvt(gB0 + ko) : z4;
            rb1 = vB1 ? ld_cvt(gB1 + ko) : z4;
        }

        const uint32_t bA = baseA + buf * 8192;
        const uint32_t bB = baseB + buf * 8192;
#pragma unroll
        for (int ks = 0; ks < 2; ks++) {
            uint32_t a[4][4];
#pragma unroll
            for (int mt = 0; mt < 4; mt++) {
                int row = wm * 64 + mt * 16 + ((lane >> 4) << 3) + (lane & 7);
                int chunk = ks * 2 + ((lane >> 3) & 1);
                uint32_t addr = bA + (uint32_t)swz(row, chunk) * 16;
                uint32_t r0, r1, r2, r3;
                ldsm4(addr, r0, r1, r2, r3);
                // mma operand order a0,a1,a2,a3 = (g,t),(g+8,t),(g,t+4),(g+8,t+4)
                a[mt][0] = r0; a[mt][1] = r2; a[mt][2] = r1; a[mt][3] = r3;
            }
            uint32_t b[4][2];
#pragma unroll
            for (int np = 0; np < 2; np++) {
                int nt0 = wn * 4 + np * 2;
                int row = (nt0 + (lane >> 4)) * 8 + (lane & 7);
                int chunk = ks * 2 + ((lane >> 3) & 1);
                uint32_t addr = bB + (uint32_t)swz(row, chunk) * 16;
                uint32_t q0, q1, q2, q3;
                ldsm4(addr, q0, q1, q2, q3);
                b[np * 2][0] = q0; b[np * 2][1] = q1;
                b[np * 2 + 1][0] = q2; b[np * 2 + 1][1] = q3;
            }
#pragma unroll
            for (int mt = 0; mt < 4; mt++)
#pragma unroll
                for (int nt = 0; nt < 4; nt++)
                    mma_tf32(acc[mt][nt], a[mt], b[nt]);
        }

        if (more) {
            const int nb = buf ^ 1;
            smA[nb][dA0] = ra0; smA[nb][dA1] = ra1;
            smB[nb][dA0] = rb0; smB[nb][dA1] = rb1;
        }
        __syncthreads();
    }

    // epilogue
    const int g = lane >> 2, t = lane & 3;
#pragma unroll
    for (int mt = 0; mt < 4; mt++) {
#pragma unroll
        for (int nt = 0; nt < 4; nt++) {
            int r0 = bm * 128 + wm * 64 + mt * 16 + g;
            int c0 = bn * 128 + wn * 32 + nt * 8 + 2 * t;
            if (c0 < N) {
                float2 v01 = make_float2(acc[mt][nt][0], acc[mt][nt][1]);
                float2 v23 = make_float2(acc[mt][nt][2], acc[mt][nt][3]);
                *(float2*)&C[(size_t)r0 * ldc + c0] = v01;
                *(float2*)&C[(size_t)(r0 + 8) * ldc + c0] = v23;
            }
        }
    }
}

// ---------------- rmsnorm ----------------
__global__ void rmsnorm_kernel(const float* __restrict__ x, int ldx,
                               const float* __restrict__ w,
                               float* __restrict__ out, int ldo, int dim)
{
    const int row = blockIdx.x;
    const float* xr = x + (size_t)row * ldx;
    float ss = 0.f;
    for (int i = threadIdx.x; i < dim; i += blockDim.x) { float v = xr[i]; ss += v * v; }
    __shared__ float red[256];
    red[threadIdx.x] = ss;
    __syncthreads();
    for (int s = 128; s > 0; s >>= 1) {
        if (threadIdx.x < s) red[threadIdx.x] += red[threadIdx.x + s];
        __syncthreads();
    }
    const float inv = rsqrtf(red[0] / (float)dim + EPS_);
    float* o = out + (size_t)row * ldo;
    for (int i = threadIdx.x; i < dim; i += blockDim.x) o[i] = xr[i] * inv * w[i];
}

// ---------------- RoPE + pack q_full / k_full as [H][T][DQK] ----------------
__global__ void rope_pack_kernel(const float* __restrict__ q,
                                 const float* __restrict__ kv,
                                 const float* __restrict__ ckv,
                                 const float* __restrict__ cosb,
                                 const float* __restrict__ sinb,
                                 float* __restrict__ qfull,
                                 float* __restrict__ kfull)
{
    const int t = blockIdx.x, h = blockIdx.y, j = threadIdx.x;  // j in [0,192)
    const size_t o = ((size_t)h * T_ + t) * DQK_ + j;
    float qv, kvv;
    if (j < DN_) {
        qv  = q[(size_t)t * (H_ * DQK_) + h * DQK_ + j];
        kvv = kv[(size_t)t * (H_ * (DN_ + DV_)) + h * (DN_ + DV_) + j];
    } else {
        const int jj = j - DN_;
        const int p  = (jj < DR_ / 2) ? jj : jj - DR_ / 2;
        const float c = cosb[(size_t)t * DR_ + jj];
        const float s = sinb[(size_t)t * DR_ + jj];
        const size_t qb = (size_t)t * (H_ * DQK_) + h * DQK_ + DN_;
        const size_t kb = (size_t)t * (KVLR_ + DR_) + KVLR_;
        const float qe = q[qb + 2 * p], qo = q[qb + 2 * p + 1];
        const float ke = ckv[kb + 2 * p], ko = ckv[kb + 2 * p + 1];
        if (jj < DR_ / 2) { qv = qe * c - qo * s;  kvv = ke * c - ko * s; }
        else              { qv = qo * c + qe * s;  kvv = ko * c + ke * s; }
    }
    qfull[o] = qv;
    kfull[o] = kvv;
}

// ---------------- causal softmax in place (scores -> probs) ----------------
__global__ void softmax_causal_kernel(float* __restrict__ scores)
{
    const int q = blockIdx.x, h = blockIdx.y;
    float* row = scores + ((size_t)h * T_ + q) * T_;
    const int len = q + 1;
    const float scale = 0.07216878364870323f;  // 192^-0.5
    const int tid = threadIdx.x;
    __shared__ float red[256];

    float m = -INFINITY;
    for (int i = tid; i < len; i += 256) m = fmaxf(m, row[i] * scale);
    red[tid] = m; __syncthreads();
    for (int s = 128; s > 0; s >>= 1) {
        if (tid < s) red[tid] = fmaxf(red[tid], red[tid + s]);
        __syncthreads();
    }
    m = red[0]; __syncthreads();

    float sum = 0.f;
    for (int i = tid; i < len; i += 256) {
        float e = expf(row[i] * scale - m);
        row[i] = e;
        sum += e;
    }
    red[tid] = sum; __syncthreads();
    for (int s = 128; s > 0; s >>= 1) {
        if (tid < s) red[tid] += red[tid + s];
        __syncthreads();
    }
    const float rinv = 1.f / red[0];
    for (int i = tid; i < len; i += 256) row[i] *= rinv;
    // zero tail up to 128-aligned boundary for the PV GEMM
    const int bound = ((q / 128) + 1) * 128;
    for (int i = len + tid; i < bound; i += 256) row[i] = 0.f;
}

// ---------------- pack V^T as [H][DV][T] ----------------
__global__ void pack_vt_kernel(const float* __restrict__ kv, float* __restrict__ vt)
{
    size_t i = (size_t)blockIdx.x * blockDim.x + threadIdx.x;
    const size_t n = (size_t)H_ * DV_ * T_;
    if (i >= n) return;
    const int t = (int)(i % T_);
    const size_t r = i / T_;
    const int d = (int)(r % DV_);
    const int h = (int)(r / DV_);
    vt[i] = kv[(size_t)t * (H_ * (DN_ + DV_)) + h * (DN_ + DV_) + DN_ + d];
}

// ---------------- elementwise ----------------
__global__ void add_kernel(const float* __restrict__ a, const float* __restrict__ b,
                           float* __restrict__ o, size_t n)
{
    size_t i = (size_t)blockIdx.x * blockDim.x + threadIdx.x;
    if (i < n) o[i] = a[i] + b[i];
}

__global__ void silu_mul_kernel(float* __restrict__ gate, const float* __restrict__ up, size_t n)
{
    size_t i = (size_t)blockIdx.x * blockDim.x + threadIdx.x;
    if (i < n) {
        float g = gate[i];
        gate[i] = (g / (1.f + expf(-g))) * up[i];
    }
}

// ---------------- host driver ----------------
static inline void* sym(const void* s)
{
    void* p = nullptr;
    cudaGetSymbolAddress(&p, s);
    return p;
}

extern "C" void kernel_launch(void* const* d_in, const int* in_sizes, int n_in,
                              void* d_out, int out_size)
{
    const float* hidden  = (const float*)d_in[0];
    const float* cosb    = (const float*)d_in[1];
    const float* sinb    = (const float*)d_in[2];
    const float* ln_in   = (const float*)d_in[3];
    const float* w_q_a   = (const float*)d_in[4];
    const float* ln_q_a  = (const float*)d_in[5];
    const float* w_q_b   = (const float*)d_in[6];
    const float* w_kv_a  = (const float*)d_in[7];
    const float* ln_kv_a = (const float*)d_in[8];
    const float* w_kv_b  = (const float*)d_in[9];
    const float* w_o     = (const float*)d_in[10];
    const float* ln_post = (const float*)d_in[11];
    const float* w_gate  = (const float*)d_in[12];
    const float* w_up    = (const float*)d_in[13];
    const float* w_down  = (const float*)d_in[14];
    float* out = (float*)d_out;

    float* h     = (float*)sym(g_h);
    float* qa    = (float*)sym(g_qa);
    float* q     = (float*)sym(g_q);
    float* ckv   = (float*)sym(g_ckv);
    float* ckvn  = (float*)sym(g_ckvn);
    float* kv    = (float*)sym(g_kv);
    float* qfull = (float*)sym(g_qfull);
    float* kfull = (float*)sym(g_kfull);
    float* sc    = (float*)sym(g_scores);
    float* vt    = (float*)sym(g_vt);
    float* attn  = (float*)sym(g_attn);
    float* res2  = (float*)sym(g_res2);
    float* h2    = (float*)sym(g_h2);
    float* gate  = (float*)sym(g_gate);
    float* up    = (float*)sym(g_up);

    const int NB = 256;
    auto grid2 = [](int M, int N) { return dim3((N + 127) / 128, M / 128, 1); };

    // 1. input rmsnorm
    rmsnorm_kernel<<<T_, NB>>>(hidden, HID_, ln_in, h, HID_, HID_);
    // 2. q_a = h @ w_q_a^T
    gemm_tf32<<<grid2(T_, QLR_), NB>>>(h, HID_, 0, w_q_a, HID_, 0, qa, QLR_, 0, T_, QLR_, HID_, 0);
    // 3. rmsnorm q_a (in place)
    rmsnorm_kernel<<<T_, NB>>>(qa, QLR_, ln_q_a, qa, QLR_, QLR_);
    // 4. q = qa @ w_q_b^T
    gemm_tf32<<<grid2(T_, H_ * DQK_), NB>>>(qa, QLR_, 0, w_q_b, QLR_, 0, q, H_ * DQK_, 0,
                                            T_, H_ * DQK_, QLR_, 0);
    // 5. ckv = h @ w_kv_a^T
    gemm_tf32<<<grid2(T_, KVLR_ + DR_), NB>>>(h, HID_, 0, w_kv_a, HID_, 0, ckv, KVLR_ + DR_, 0,
                                              T_, KVLR_ + DR_, HID_, 0);
    // 6. rmsnorm c_kv slice
    rmsnorm_kernel<<<T_, NB>>>(ckv, KVLR_ + DR_, ln_kv_a, ckvn, KVLR_, KVLR_);
    // 7. kv = ckvn @ w_kv_b^T
    gemm_tf32<<<grid2(T_, H_ * (DN_ + DV_)), NB>>>(ckvn, KVLR_, 0, w_kv_b, KVLR_, 0,
                                                   kv, H_ * (DN_ + DV_), 0,
                                                   T_, H_ * (DN_ + DV_), KVLR_, 0);
    // 8. RoPE + pack
    rope_pack_kernel<<<dim3(T_, H_), DQK_>>>(q, kv, ckv, cosb, sinb, qfull, kfull);
    // 9. scores = q_full @ k_full^T (per head, causal tile skip)
    gemm_tf32<<<dim3(T_ / 128, T_ / 128, H_), NB>>>(qfull, DQK_, (size_t)T_ * DQK_,
                                                    kfull, DQK_, (size_t)T_ * DQK_,
                                                    sc, T_, (size_t)T_ * T_,
                                                    T_, T_, DQK_, 1);
    // 10. causal softmax
    softmax_causal_kernel<<<dim3(T_, H_), NB>>>(sc);
    // 11. pack V^T
    {
        size_t n = (size_t)H_ * DV_ * T_;
        pack_vt_kernel<<<(unsigned)((n + NB - 1) / NB), NB>>>(kv, vt);
    }
    // 12. attn = probs @ V (direct [T, H*DV] layout)
    gemm_tf32<<<dim3(1, T_ / 128, H_), NB>>>(sc, T_, (size_t)T_ * T_,
                                             vt, T_, (size_t)DV_ * T_,
                                             attn, H_ * DV_, (size_t)DV_,
                                             T_, DV_, T_, 2);
    // 13. o = attn @ w_o^T (reuse h)
    gemm_tf32<<<grid2(T_, HID_), NB>>>(attn, H_ * DV_, 0, w_o, H_ * DV_, 0, h, HID_, 0,
                                       T_, HID_, H_ * DV_, 0);
    // 14. res2 = hidden + o
    {
        size_t n = (size_t)T_ * HID_;
        add_kernel<<<(unsigned)((n + NB - 1) / NB), NB>>>(hidden, h, res2, n);
    }
    // 15. h2 = rmsnorm(res2)
    rmsnorm_kernel<<<T_, NB>>>(res2, HID_, ln_post, h2, HID_, HID_);
    // 16/17. gate, up
    gemm_tf32<<<grid2(T_, INTER_), NB>>>(h2, HID_, 0, w_gate, HID_, 0, gate, INTER_, 0,
                                         T_, INTER_, HID_, 0);
    gemm_tf32<<<grid2(T_, INTER_), NB>>>(h2, HID_, 0, w_up, HID_, 0, up, INTER_, 0,
                                         T_, INTER_, HID_, 0);
    // 18. act = silu(gate) * up
    {
        size_t n = (size_t)T_ * INTER_;
        silu_mul_kernel<<<(unsigned)((n + NB - 1) / NB), NB>>>(gate, up, n);
    }
    // 19. down = act @ w_down^T (reuse h)
    gemm_tf32<<<grid2(T_, HID_), NB>>>(gate, INTER_, 0, w_down, INTER_, 0, h, HID_, 0,
                                       T_, HID_, INTER_, 0);
    // 20. out = res2 + down
    {
        size_t n = (size_t)T_ * HID_;
        add_kernel<<<(unsigned)((n + NB - 1) / NB), NB>>>(res2, h, out, n);
    }
}

// round 5
// speedup vs baseline: 4.0356x; 1.4045x over previous
#include <cuda_runtime.h>
#include <cuda_bf16.h>
#include <math.h>
#include <stdint.h>

// ---------------- problem constants ----------------
#define T_    2048
#define HID_  2048
#define H_    16
#define DN_   128
#define DR_   64
#define DQK_  192
#define DV_   128
#define QLR_  1536
#define KVLR_ 512
#define INTER_ 10944
#define EPS_  1e-6f

// ---------------- scratch (static device globals) ----------------
__device__ float g_h[(size_t)T_ * HID_];
__device__ float g_qa[(size_t)T_ * QLR_];
__device__ float g_q[(size_t)T_ * H_ * DQK_];
__device__ float g_ckv[(size_t)T_ * (KVLR_ + DR_)];
__device__ float g_ckvn[(size_t)T_ * KVLR_];
__device__ float g_kv[(size_t)T_ * H_ * (DN_ + DV_)];
__device__ float g_qfull[(size_t)H_ * T_ * DQK_];
__device__ float g_kfull[(size_t)H_ * T_ * DQK_];
__device__ float g_scores[(size_t)H_ * T_ * T_];
__device__ float g_vt[(size_t)H_ * DV_ * T_];
__device__ float g_attn[(size_t)T_ * H_ * DV_];
__device__ float g_res2[(size_t)T_ * HID_];
__device__ float g_h2[(size_t)T_ * HID_];
__device__ float g_gate[(size_t)T_ * INTER_];
__device__ float g_up[(size_t)T_ * INTER_];
// tf32-rounded weight copies
__device__ float g_wqa[(size_t)QLR_ * HID_];
__device__ float g_wqb[(size_t)H_ * DQK_ * QLR_];
__device__ float g_wkva[(size_t)(KVLR_ + DR_) * HID_];
__device__ float g_wkvb[(size_t)H_ * (DN_ + DV_) * KVLR_];
__device__ float g_wo[(size_t)HID_ * H_ * DV_];
__device__ float g_wgate[(size_t)INTER_ * HID_];
__device__ float g_wup[(size_t)INTER_ * HID_];
__device__ float g_wdown[(size_t)HID_ * INTER_];

// ---------------- helpers ----------------
__device__ __forceinline__ uint32_t f2tf32(float f) {
    uint32_t u;
    asm("cvt.rna.tf32.f32 %0, %1;" : "=r"(u) : "f"(f));
    return u;
}
__device__ __forceinline__ float tf32r(float f) { return __uint_as_float(f2tf32(f)); }

__device__ __forceinline__ uint32_t smem_u32(const void* p) {
    uint32_t a;
    asm("{ .reg .u64 t; cvta.to.shared.u64 t, %1; cvt.u32.u64 %0, t; }" : "=r"(a) : "l"(p));
    return a;
}
__device__ __forceinline__ void ldsm4(uint32_t addr, uint32_t& r0, uint32_t& r1,
                                      uint32_t& r2, uint32_t& r3) {
    asm volatile("ldmatrix.sync.aligned.m8n8.x4.shared.b16 {%0,%1,%2,%3}, [%4];"
                 : "=r"(r0), "=r"(r1), "=r"(r2), "=r"(r3) : "r"(addr));
}
__device__ __forceinline__ void mma_tf32(float* c, const uint32_t* a, const uint32_t* b) {
    asm volatile(
        "mma.sync.aligned.m16n8k8.row.col.f32.tf32.tf32.f32 "
        "{%0,%1,%2,%3}, {%4,%5,%6,%7}, {%8,%9}, {%0,%1,%2,%3};"
        : "+f"(c[0]), "+f"(c[1]), "+f"(c[2]), "+f"(c[3])
        : "r"(a[0]), "r"(a[1]), "r"(a[2]), "r"(a[3]), "r"(b[0]), "r"(b[1]));
}
__device__ __forceinline__ void cp16(uint32_t smaddr, const void* gaddr, int vbytes) {
    asm volatile("cp.async.cg.shared.global [%0], [%1], 16, %2;"
                 :: "r"(smaddr), "l"(gaddr), "r"(vbytes) : "memory");
}
#define CP_COMMIT() asm volatile("cp.async.commit_group;" ::: "memory")
#define CP_WAIT2()  asm volatile("cp.async.wait_group 2;" ::: "memory")

// ================= tf32 mma.sync GEMM: C = A * B^T =================
// Block 128x128, 8 warps (2x4), warp tile 64x32, BK=32, 3-stage cp.async.
// All operands must already be tf32-valued floats in gmem.
// mode 0 dense; mode 1 causal tile skip; mode 2 causal K-truncate.
#define GB_STAGE_BYTES 32768
#define GB_SMEM (3 * GB_STAGE_BYTES)

__global__ __launch_bounds__(256, 2) void gemm_mma(
    const float* __restrict__ A, int lda, size_t sA,
    const float* __restrict__ B, int ldb, size_t sB,
    float* __restrict__ C, int ldc, size_t sC,
    int M, int N, int K, int mode, int roundC)
{
    const int bm = blockIdx.y, bn = blockIdx.x, bz = blockIdx.z;
    if (mode == 1 && bn > bm) return;
    int kEnd = K;
    if (mode == 2) { int ke = (bm + 1) * 128; kEnd = ke < K ? ke : K; }

    A += (size_t)bz * sA;
    B += (size_t)bz * sB;
    C += (size_t)bz * sC;

    extern __shared__ char smem[];
    const uint32_t smem_base = smem_u32(smem);
    const int tid = threadIdx.x, wid = tid >> 5, lane = tid & 31;
    const int wm = wid & 1, wn = wid >> 1;
    const int row0 = bm * 128, nrow0 = bn * 128;
    const int nIter = kEnd >> 5;

    // loader: thread handles 4 A-chunks + 4 B-chunks of 16B each
    const int lr = tid >> 3;          // base row (0..31), +32*j
    const int lc = tid & 7;           // chunk 0..7
    const uint32_t lsw = (uint32_t)((lc ^ (lr & 7)) << 4);

    auto load_stage = [&](int it, int s) {
        const int k0 = it << 5;
        const uint32_t sA_ = smem_base + s * GB_STAGE_BYTES;
        const uint32_t sB_ = sA_ + 16384;
#pragma unroll
        for (int j = 0; j < 4; j++) {
            const int r = lr + j * 32;
            cp16(sA_ + (uint32_t)r * 128 + lsw,
                 A + (size_t)(row0 + r) * lda + k0 + lc * 4, 16);
        }
#pragma unroll
        for (int j = 0; j < 4; j++) {
            const int r = lr + j * 32;
            const int gr = nrow0 + r;
            cp16(sB_ + (uint32_t)r * 128 + lsw,
                 B + (size_t)(gr < N ? gr : 0) * ldb + k0 + lc * 4, gr < N ? 16 : 0);
        }
        CP_COMMIT();
    };

    float acc[4][4][4];
#pragma unroll
    for (int i = 0; i < 4; i++)
#pragma unroll
        for (int j = 0; j < 4; j++)
#pragma unroll
            for (int l = 0; l < 4; l++) acc[i][j][l] = 0.f;

    load_stage(0, 0);
    if (1 < nIter) load_stage(1, 1); else CP_COMMIT();

    const int klo = (lane >> 3) & 1;
    const int arow_lo = ((lane >> 4) << 3) + (lane & 7);   // 0..15
    const int l7 = lane & 7;

    for (int it = 0; it < nIter; ++it) {
        if (it + 2 < nIter) load_stage(it + 2, (it + 2) % 3); else CP_COMMIT();
        CP_WAIT2();
        __syncthreads();

        const uint32_t bA = smem_base + (it % 3) * GB_STAGE_BYTES;
        const uint32_t bB = bA + 16384;
#pragma unroll
        for (int ks = 0; ks < 4; ks++) {
            const int chk = ks * 2 + klo;
            uint32_t a[4][4];
#pragma unroll
            for (int mt = 0; mt < 4; mt++) {
                const int row = wm * 64 + mt * 16 + arow_lo;
                const uint32_t addr = bA + (uint32_t)row * 128 + (uint32_t)((chk ^ l7) << 4);
                uint32_t r0, r1, r2, r3;
                ldsm4(addr, r0, r1, r2, r3);
                a[mt][0] = r0; a[mt][1] = r2; a[mt][2] = r1; a[mt][3] = r3;
            }
            uint32_t b[4][2];
#pragma unroll
            for (int np = 0; np < 2; np++) {
                const int row = (wn * 4 + np * 2 + (lane >> 4)) * 8 + l7;
                const uint32_t addr = bB + (uint32_t)row * 128 + (uint32_t)((chk ^ l7) << 4);
                uint32_t q0, q1, q2, q3;
                ldsm4(addr, q0, q1, q2, q3);
                b[np * 2][0] = q0;     b[np * 2][1] = q1;
                b[np * 2 + 1][0] = q2; b[np * 2 + 1][1] = q3;
            }
#pragma unroll
            for (int mt = 0; mt < 4; mt++)
#pragma unroll
                for (int nt = 0; nt < 4; nt++)
                    mma_tf32(acc[mt][nt], a[mt], b[nt]);
        }
        __syncthreads();
    }

    // epilogue
    const int g = lane >> 2, t = lane & 3;
#pragma unroll
    for (int mt = 0; mt < 4; mt++) {
#pragma unroll
        for (int nt = 0; nt < 4; nt++) {
            int r0 = row0 + wm * 64 + mt * 16 + g;
            int c0 = nrow0 + wn * 32 + nt * 8 + 2 * t;
            if (c0 < N) {
                float v0 = acc[mt][nt][0], v1 = acc[mt][nt][1];
                float v2 = acc[mt][nt][2], v3 = acc[mt][nt][3];
                if (roundC) { v0 = tf32r(v0); v1 = tf32r(v1); v2 = tf32r(v2); v3 = tf32r(v3); }
                *(float2*)&C[(size_t)r0 * ldc + c0] = make_float2(v0, v1);
                *(float2*)&C[(size_t)(r0 + 8) * ldc + c0] = make_float2(v2, v3);
            }
        }
    }
}

// ---------------- tf32 weight conversion ----------------
__global__ void cvt_tf32_kernel(const float* __restrict__ in, float* __restrict__ out, size_t n4)
{
    size_t i = (size_t)blockIdx.x * blockDim.x + threadIdx.x;
    if (i < n4) {
        float4 v = ((const float4*)in)[i];
        v.x = tf32r(v.x); v.y = tf32r(v.y); v.z = tf32r(v.z); v.w = tf32r(v.w);
        ((float4*)out)[i] = v;
    }
}

// ---------------- rmsnorm (tf32-rounded output) ----------------
__global__ void rmsnorm_kernel(const float* __restrict__ x, int ldx,
                               const float* __restrict__ w,
                               float* __restrict__ out, int ldo, int dim)
{
    const int row = blockIdx.x;
    const float* xr = x + (size_t)row * ldx;
    float ss = 0.f;
    for (int i = threadIdx.x; i < dim; i += blockDim.x) { float v = xr[i]; ss += v * v; }
    __shared__ float red[256];
    red[threadIdx.x] = ss;
    __syncthreads();
    for (int s = 128; s > 0; s >>= 1) {
        if (threadIdx.x < s) red[threadIdx.x] += red[threadIdx.x + s];
        __syncthreads();
    }
    const float inv = rsqrtf(red[0] / (float)dim + EPS_);
    float* o = out + (size_t)row * ldo;
    for (int i = threadIdx.x; i < dim; i += blockDim.x) o[i] = tf32r(xr[i] * inv * w[i]);
}

// ---------------- RoPE + pack (tf32-rounded) ----------------
__global__ void rope_pack_kernel(const float* __restrict__ q,
                                 const float* __restrict__ kv,
                                 const float* __restrict__ ckv,
                                 const float* __restrict__ cosb,
                                 const float* __restrict__ sinb,
                                 float* __restrict__ qfull,
                                 float* __restrict__ kfull)
{
    const int t = blockIdx.x, h = blockIdx.y, j = threadIdx.x;
    const size_t o = ((size_t)h * T_ + t) * DQK_ + j;
    float qv, kvv;
    if (j < DN_) {
        qv  = q[(size_t)t * (H_ * DQK_) + h * DQK_ + j];
        kvv = kv[(size_t)t * (H_ * (DN_ + DV_)) + h * (DN_ + DV_) + j];
    } else {
        const int jj = j - DN_;
        const int p  = (jj < DR_ / 2) ? jj : jj - DR_ / 2;
        const float c = cosb[(size_t)t * DR_ + jj];
        const float s = sinb[(size_t)t * DR_ + jj];
        const size_t qb = (size_t)t * (H_ * DQK_) + h * DQK_ + DN_;
        const size_t kb = (size_t)t * (KVLR_ + DR_) + KVLR_;
        const float qe = q[qb + 2 * p], qo = q[qb + 2 * p + 1];
        const float ke = ckv[kb + 2 * p], ko = ckv[kb + 2 * p + 1];
        if (jj < DR_ / 2) { qv = qe * c - qo * s;  kvv = ke * c - ko * s; }
        else              { qv = qo * c + qe * s;  kvv = ko * c + ke * s; }
    }
    qfull[o] = tf32r(qv);
    kfull[o] = tf32r(kvv);
}

// ---------------- causal softmax (tf32-rounded probs) ----------------
__global__ void softmax_causal_kernel(float* __restrict__ scores)
{
    const int q = blockIdx.x, h = blockIdx.y;
    float* row = scores + ((size_t)h * T_ + q) * T_;
    const int len = q + 1;
    const float scale = 0.07216878364870323f;
    const int tid = threadIdx.x;
    __shared__ float red[256];

    float m = -INFINITY;
    for (int i = tid; i < len; i += 256) m = fmaxf(m, row[i] * scale);
    red[tid] = m; __syncthreads();
    for (int s = 128; s > 0; s >>= 1) {
        if (tid < s) red[tid] = fmaxf(red[tid], red[tid + s]);
        __syncthreads();
    }
    m = red[0]; __syncthreads();

    float sum = 0.f;
    for (int i = tid; i < len; i += 256) {
        float e = expf(row[i] * scale - m);
        row[i] = e;
        sum += e;
    }
    red[tid] = sum; __syncthreads();
    for (int s = 128; s > 0; s >>= 1) {
        if (tid < s) red[tid] += red[tid + s];
        __syncthreads();
    }
    const float rinv = 1.f / red[0];
    for (int i = tid; i < len; i += 256) row[i] = tf32r(row[i] * rinv);
    const int bound = ((q / 128) + 1) * 128;
    for (int i = len + tid; i < bound; i += 256) row[i] = 0.f;
}

// ---------------- pack V^T (tf32-rounded) ----------------
__global__ void pack_vt_kernel(const float* __restrict__ kv, float* __restrict__ vt)
{
    size_t i = (size_t)blockIdx.x * blockDim.x + threadIdx.x;
    const size_t n = (size_t)H_ * DV_ * T_;
    if (i >= n) return;
    const int t = (int)(i % T_);
    const size_t r = i / T_;
    const int d = (int)(r % DV_);
    const int h = (int)(r / DV_);
    vt[i] = tf32r(kv[(size_t)t * (H_ * (DN_ + DV_)) + h * (DN_ + DV_) + DN_ + d]);
}

// ---------------- elementwise ----------------
__global__ void add_kernel(const float* __restrict__ a, const float* __restrict__ b,
                           float* __restrict__ o, size_t n)
{
    size_t i = (size_t)blockIdx.x * blockDim.x + threadIdx.x;
    if (i < n) o[i] = a[i] + b[i];
}

__global__ void silu_mul_kernel(float* __restrict__ gate, const float* __restrict__ up, size_t n)
{
    size_t i = (size_t)blockIdx.x * blockDim.x + threadIdx.x;
    if (i < n) {
        float g = gate[i];
        gate[i] = tf32r((g / (1.f + expf(-g))) * up[i]);
    }
}

// ---------------- host driver ----------------
static inline void* sym(const void* s)
{
    void* p = nullptr;
    cudaGetSymbolAddress(&p, s);
    return p;
}

extern "C" void kernel_launch(void* const* d_in, const int* in_sizes, int n_in,
                              void* d_out, int out_size)
{
    const float* hidden  = (const float*)d_in[0];
    const float* cosb    = (const float*)d_in[1];
    const float* sinb    = (const float*)d_in[2];
    const float* ln_in   = (const float*)d_in[3];
    const float* w_q_a   = (const float*)d_in[4];
    const float* ln_q_a  = (const float*)d_in[5];
    const float* w_q_b   = (const float*)d_in[6];
    const float* w_kv_a  = (const float*)d_in[7];
    const float* ln_kv_a = (const float*)d_in[8];
    const float* w_kv_b  = (const float*)d_in[9];
    const float* w_o     = (const float*)d_in[10];
    const float* ln_post = (const float*)d_in[11];
    const float* w_gate  = (const float*)d_in[12];
    const float* w_up    = (const float*)d_in[13];
    const float* w_down  = (const float*)d_in[14];
    float* out = (float*)d_out;

    float* h     = (float*)sym(g_h);
    float* qa    = (float*)sym(g_qa);
    float* q     = (float*)sym(g_q);
    float* ckv   = (float*)sym(g_ckv);
    float* ckvn  = (float*)sym(g_ckvn);
    float* kv    = (float*)sym(g_kv);
    float* qfull = (float*)sym(g_qfull);
    float* kfull = (float*)sym(g_kfull);
    float* sc    = (float*)sym(g_scores);
    float* vt    = (float*)sym(g_vt);
    float* attn  = (float*)sym(g_attn);
    float* res2  = (float*)sym(g_res2);
    float* h2    = (float*)sym(g_h2);
    float* gate  = (float*)sym(g_gate);
    float* up    = (float*)sym(g_up);
    float* wqa   = (float*)sym(g_wqa);
    float* wqb   = (float*)sym(g_wqb);
    float* wkva  = (float*)sym(g_wkva);
    float* wkvb  = (float*)sym(g_wkvb);
    float* wo    = (float*)sym(g_wo);
    float* wgt   = (float*)sym(g_wgate);
    float* wup   = (float*)sym(g_wup);
    float* wdn   = (float*)sym(g_wdown);

    cudaFuncSetAttribute(gemm_mma, cudaFuncAttributeMaxDynamicSharedMemorySize, GB_SMEM);

    const int NB = 256;
    const int SH = GB_SMEM;
    auto grid2 = [](int M, int N) { return dim3((N + 127) / 128, M / 128, 1); };
    auto cvt = [&](const float* src, float* dst, size_t n) {
        size_t n4 = n / 4;
        cvt_tf32_kernel<<<(unsigned)((n4 + 255) / 256), 256>>>(src, dst, n4);
    };

    // 0. one-time weight rounding to tf32 values
    cvt(w_q_a, wqa, (size_t)QLR_ * HID_);
    cvt(w_q_b, wqb, (size_t)H_ * DQK_ * QLR_);
    cvt(w_kv_a, wkva, (size_t)(KVLR_ + DR_) * HID_);
    cvt(w_kv_b, wkvb, (size_t)H_ * (DN_ + DV_) * KVLR_);
    cvt(w_o, wo, (size_t)HID_ * H_ * DV_);
    cvt(w_gate, wgt, (size_t)INTER_ * HID_);
    cvt(w_up, wup, (size_t)INTER_ * HID_);
    cvt(w_down, wdn, (size_t)HID_ * INTER_);

    // 1. input rmsnorm (rounded output)
    rmsnorm_kernel<<<T_, NB>>>(hidden, HID_, ln_in, h, HID_, HID_);
    // 2. q_a = h @ w_q_a^T
    gemm_mma<<<grid2(T_, QLR_), NB, SH>>>(h, HID_, 0, wqa, HID_, 0, qa, QLR_, 0,
                                          T_, QLR_, HID_, 0, 0);
    // 3. rmsnorm q_a (in place, rounded)
    rmsnorm_kernel<<<T_, NB>>>(qa, QLR_, ln_q_a, qa, QLR_, QLR_);
    // 4. q = qa @ w_q_b^T
    gemm_mma<<<grid2(T_, H_ * DQK_), NB, SH>>>(qa, QLR_, 0, wqb, QLR_, 0, q, H_ * DQK_, 0,
                                               T_, H_ * DQK_, QLR_, 0, 0);
    // 5. ckv = h @ w_kv_a^T
    gemm_mma<<<grid2(T_, KVLR_ + DR_), NB, SH>>>(h, HID_, 0, wkva, HID_, 0, ckv, KVLR_ + DR_, 0,
                                                 T_, KVLR_ + DR_, HID_, 0, 0);
    // 6. rmsnorm c_kv slice (rounded)
    rmsnorm_kernel<<<T_, NB>>>(ckv, KVLR_ + DR_, ln_kv_a, ckvn, KVLR_, KVLR_);
    // 7. kv = ckvn @ w_kv_b^T
    gemm_mma<<<grid2(T_, H_ * (DN_ + DV_)), NB, SH>>>(ckvn, KVLR_, 0, wkvb, KVLR_, 0,
                                                      kv, H_ * (DN_ + DV_), 0,
                                                      T_, H_ * (DN_ + DV_), KVLR_, 0, 0);
    // 8. RoPE + pack (rounded)
    rope_pack_kernel<<<dim3(T_, H_), DQK_>>>(q, kv, ckv, cosb, sinb, qfull, kfull);
    // 9. scores = q_full @ k_full^T (causal tile skip)
    gemm_mma<<<dim3(T_ / 128, T_ / 128, H_), NB, SH>>>(qfull, DQK_, (size_t)T_ * DQK_,
                                                       kfull, DQK_, (size_t)T_ * DQK_,
                                                       sc, T_, (size_t)T_ * T_,
                                                       T_, T_, DQK_, 1, 0);
    // 10. causal softmax (rounded probs)
    softmax_causal_kernel<<<dim3(T_, H_), NB>>>(sc);
    // 11. pack V^T (rounded)
    {
        size_t n = (size_t)H_ * DV_ * T_;
        pack_vt_kernel<<<(unsigned)((n + NB - 1) / NB), NB>>>(kv, vt);
    }
    // 12. attn = probs @ V (rounded output: feeds o-proj)
    gemm_mma<<<dim3(1, T_ / 128, H_), NB, SH>>>(sc, T_, (size_t)T_ * T_,
                                                vt, T_, (size_t)DV_ * T_,
                                                attn, H_ * DV_, (size_t)DV_,
                                                T_, DV_, T_, 2, 1);
    // 13. o = attn @ w_o^T (reuse h)
    gemm_mma<<<grid2(T_, HID_), NB, SH>>>(attn, H_ * DV_, 0, wo, H_ * DV_, 0, h, HID_, 0,
                                          T_, HID_, H_ * DV_, 0, 0);
    // 14. res2 = hidden + o
    {
        size_t n = (size_t)T_ * HID_;
        add_kernel<<<(unsigned)((n + NB - 1) / NB), NB>>>(hidden, h, res2, n);
    }
    // 15. h2 = rmsnorm(res2) (rounded)
    rmsnorm_kernel<<<T_, NB>>>(res2, HID_, ln_post, h2, HID_, HID_);
    // 16/17. gate, up
    gemm_mma<<<grid2(T_, INTER_), NB, SH>>>(h2, HID_, 0, wgt, HID_, 0, gate, INTER_, 0,
                                            T_, INTER_, HID_, 0, 0);
    gemm_mma<<<grid2(T_, INTER_), NB, SH>>>(h2, HID_, 0, wup, HID_, 0, up, INTER_, 0,
                                            T_, INTER_, HID_, 0, 0);
    // 18. act = silu(gate) * up (rounded)
    {
        size_t n = (size_t)T_ * INTER_;
        silu_mul_kernel<<<(unsigned)((n + NB - 1) / NB), NB>>>(gate, up, n);
    }
    // 19. down = act @ w_down^T (reuse h)
    gemm_mma<<<grid2(T_, HID_), NB, SH>>>(gate, INTER_, 0, wdn, INTER_, 0, h, HID_, 0,
                                          T_, HID_, INTER_, 0, 0);
    // 20. out = res2 + down
    {
        size_t n = (size_t)T_ * HID_;
        add_kernel<<<(unsigned)((n + NB - 1) / NB), NB>>>(res2, h, out, n);
    }
}